// round 1
// baseline (speedup 1.0000x reference)
#include <cuda_runtime.h>
#include <cuda_bf16.h>
#include <math.h>

// Problem constants
#define BATCH_ 32
#define RESO_ 56
#define L_ (RESO_ * RESO_)          // 3136
#define C_ 128
#define M_ (BATCH_ * L_)            // 100352 rows
#define HID_ 512
#define TOK_ 112                    // window tokens (56*2)
#define NWIN_ 28                    // windows per batch per branch
#define SLOT_STRIDE_ 36             // padded head-dim stride in smem

// Scratch buffers (device globals: allocation-free)
__device__ float g_ln  [(size_t)M_ * C_];
__device__ float g_qkv [(size_t)M_ * 3 * C_];
__device__ float g_attn[(size_t)M_ * C_];
__device__ float g_x   [(size_t)M_ * C_];
__device__ float g_hid [(size_t)M_ * HID_];

// ---------------------------------------------------------------------------
// LayerNorm: one warp per row of 128
// ---------------------------------------------------------------------------
__global__ __launch_bounds__(256) void ln_kernel(
    const float* __restrict__ in, const float* __restrict__ g,
    const float* __restrict__ b, float* __restrict__ out)
{
    int warp = (blockIdx.x * blockDim.x + threadIdx.x) >> 5;
    int lane = threadIdx.x & 31;
    if (warp >= M_) return;
    float4 v = ((const float4*)(in + (size_t)warp * C_))[lane];
    float s = v.x + v.y + v.z + v.w;
    #pragma unroll
    for (int o = 16; o; o >>= 1) s += __shfl_xor_sync(0xffffffffu, s, o);
    float mu = s * (1.0f / C_);
    float dx = v.x - mu, dy = v.y - mu, dz = v.z - mu, dw = v.w - mu;
    float q = dx*dx + dy*dy + dz*dz + dw*dw;
    #pragma unroll
    for (int o = 16; o; o >>= 1) q += __shfl_xor_sync(0xffffffffu, q, o);
    float rs = rsqrtf(q * (1.0f / C_) + 1e-5f);
    float4 gg = ((const float4*)g)[lane];
    float4 bb = ((const float4*)b)[lane];
    float4 o4;
    o4.x = dx * rs * gg.x + bb.x;
    o4.y = dy * rs * gg.y + bb.y;
    o4.z = dz * rs * gg.z + bb.z;
    o4.w = dw * rs * gg.w + bb.w;
    ((float4*)(out + (size_t)warp * C_))[lane] = o4;
}

// ---------------------------------------------------------------------------
// SGEMM: C[M,N] = A[M,K] @ B[K,N]  (+ epilogue)
// mode 0: plain   mode 1: +bias +res   mode 2: +bias, GELU   mode 3: +bias +res
// BM=128, BN=64, BK=16, 256 threads, 8x4 per-thread tile.
// All dims divide exactly; no bounds checks.
// ---------------------------------------------------------------------------
#define BM 128
#define BN 64
#define BK 16

__global__ __launch_bounds__(256) void sgemm_kernel(
    const float* __restrict__ A, const float* __restrict__ Bm,
    float* __restrict__ C, int M, int N, int K,
    const float* __restrict__ bias, const float* __restrict__ res, int mode)
{
    __shared__ float As[BK][BM + 4];
    __shared__ float Bs[BK][BN];

    int tid = threadIdx.x;
    int tx = tid & 15;   // N direction
    int ty = tid >> 4;   // M direction
    int mBase = blockIdx.y * BM;
    int nBase = blockIdx.x * BN;

    int ar = tid >> 2;   // 0..63
    int ac = tid & 3;    // 0..3 (float4 groups)
    int br = tid >> 4;   // 0..15
    int bc = tid & 15;   // 0..15

    float acc[8][4];
    #pragma unroll
    for (int i = 0; i < 8; i++)
        #pragma unroll
        for (int j = 0; j < 4; j++) acc[i][j] = 0.0f;

    int nkt = K / BK;
    for (int kt = 0; kt < nkt; kt++) {
        #pragma unroll
        for (int h = 0; h < 2; h++) {
            int row = ar + h * 64;
            float4 a = *(const float4*)(A + (size_t)(mBase + row) * K + kt * BK + ac * 4);
            As[ac * 4 + 0][row] = a.x;
            As[ac * 4 + 1][row] = a.y;
            As[ac * 4 + 2][row] = a.z;
            As[ac * 4 + 3][row] = a.w;
        }
        float4 bv = *(const float4*)(Bm + (size_t)(kt * BK + br) * N + nBase + bc * 4);
        *(float4*)&Bs[br][bc * 4] = bv;
        __syncthreads();

        #pragma unroll
        for (int k = 0; k < BK; k++) {
            float4 a0 = *(const float4*)&As[k][ty * 8];
            float4 a1 = *(const float4*)&As[k][ty * 8 + 4];
            float4 b0 = *(const float4*)&Bs[k][tx * 4];
            float am[8] = {a0.x, a0.y, a0.z, a0.w, a1.x, a1.y, a1.z, a1.w};
            float bn[4] = {b0.x, b0.y, b0.z, b0.w};
            #pragma unroll
            for (int i = 0; i < 8; i++)
                #pragma unroll
                for (int j = 0; j < 4; j++)
                    acc[i][j] += am[i] * bn[j];
        }
        __syncthreads();
    }

    // Epilogue
    float4 bb = make_float4(0.f, 0.f, 0.f, 0.f);
    if (mode >= 1) bb = *(const float4*)(bias + nBase + tx * 4);
    #pragma unroll
    for (int i = 0; i < 8; i++) {
        int row = mBase + ty * 8 + i;
        int col = nBase + tx * 4;
        float4 v = make_float4(acc[i][0] + bb.x, acc[i][1] + bb.y,
                               acc[i][2] + bb.z, acc[i][3] + bb.w);
        if (mode == 1 || mode == 3) {
            float4 r = *(const float4*)(res + (size_t)row * N + col);
            v.x += r.x; v.y += r.y; v.z += r.z; v.w += r.w;
        } else if (mode == 2) {
            v.x = 0.5f * v.x * (1.0f + erff(v.x * 0.70710678118654752f));
            v.y = 0.5f * v.y * (1.0f + erff(v.y * 0.70710678118654752f));
            v.z = 0.5f * v.z * (1.0f + erff(v.z * 0.70710678118654752f));
            v.w = 0.5f * v.w * (1.0f + erff(v.w * 0.70710678118654752f));
        }
        *(float4*)(C + (size_t)row * N + col) = v;
    }
}

// ---------------------------------------------------------------------------
// Fused window attention + LEPE.
// One block per (branch, window, head): 2 * (32*28) * 2 = 3584 blocks.
// Block: 128 threads; thread t < 112 owns query token t.
// Branch 0: windows 56x2 (H_sp=56, W_sp=2), channels [0,64)
// Branch 1: windows 2x56 (H_sp=2,  W_sp=56), channels [64,128)
// Per-branch heads: 2, head dim 32, scale = 1/sqrt(32).
// ---------------------------------------------------------------------------
__global__ __launch_bounds__(128) void attn_kernel(
    const float* __restrict__ qkv,
    const float* __restrict__ cw0, const float* __restrict__ cb0,
    const float* __restrict__ cw1, const float* __restrict__ cb1,
    float* __restrict__ outp)
{
    extern __shared__ float sm[];
    float* Qs = sm;                        // 112 * 36
    float* Ks = sm + TOK_ * SLOT_STRIDE_;
    float* Vs = sm + 2 * TOK_ * SLOT_STRIDE_;
    float* Ss = sm + 3 * TOK_ * SLOT_STRIDE_;  // 112 * 113

    int bid = blockIdx.x;
    int branch = bid / 1792;
    int rem = bid - branch * 1792;
    int win = rem >> 1;
    int head = rem & 1;
    int b = win / NWIN_;
    int slot = win - b * NWIN_;
    int cb = branch * 64 + head * 32;
    int tid = threadIdx.x;
    const float scale = 0.17677669529663687f;  // 32^-0.5

    // Load Q (scaled), K, V tiles
    for (int idx = tid; idx < TOK_ * 8; idx += 128) {
        int t = idx >> 3;
        int f = idx & 7;
        int pix;
        if (branch == 0) {
            pix = (t >> 1) * RESO_ + slot * 2 + (t & 1);
        } else {
            int hs = t / RESO_;
            pix = (slot * 2 + hs) * RESO_ + (t - hs * RESO_);
        }
        size_t ro = ((size_t)(b * L_ + pix)) * 384 + cb + f * 4;
        float4 q4 = *(const float4*)(qkv + ro);
        float4 k4 = *(const float4*)(qkv + ro + 128);
        float4 v4 = *(const float4*)(qkv + ro + 256);
        float* qd = Qs + t * SLOT_STRIDE_ + f * 4;
        qd[0] = q4.x * scale; qd[1] = q4.y * scale;
        qd[2] = q4.z * scale; qd[3] = q4.w * scale;
        *(float4*)(Ks + t * SLOT_STRIDE_ + f * 4) = k4;
        *(float4*)(Vs + t * SLOT_STRIDE_ + f * 4) = v4;
    }
    __syncthreads();

    if (tid < TOK_) {
        float qr[32];
        #pragma unroll
        for (int d = 0; d < 32; d++) qr[d] = Qs[tid * SLOT_STRIDE_ + d];

        float* srow = Ss + tid * 113;
        float m = -1e30f;
        for (int k = 0; k < TOK_; k++) {
            const float4* kp = (const float4*)(Ks + k * SLOT_STRIDE_);
            float s = 0.0f;
            #pragma unroll
            for (int f = 0; f < 8; f++) {
                float4 kv = kp[f];
                s += qr[f*4]   * kv.x + qr[f*4+1] * kv.y +
                     qr[f*4+2] * kv.z + qr[f*4+3] * kv.w;
            }
            srow[k] = s;
            m = fmaxf(m, s);
        }
        float sum = 0.0f;
        for (int k = 0; k < TOK_; k++) {
            float p = __expf(srow[k] - m);
            srow[k] = p;
            sum += p;
        }
        float inv = 1.0f / sum;

        float acc[32];
        #pragma unroll
        for (int d = 0; d < 32; d++) acc[d] = 0.0f;
        for (int k = 0; k < TOK_; k++) {
            float p = srow[k];
            const float4* vp = (const float4*)(Vs + k * SLOT_STRIDE_);
            #pragma unroll
            for (int f = 0; f < 8; f++) {
                float4 vv = vp[f];
                acc[f*4]   += p * vv.x;
                acc[f*4+1] += p * vv.y;
                acc[f*4+2] += p * vv.z;
                acc[f*4+3] += p * vv.w;
            }
        }

        // LEPE depthwise 3x3 within the window (zero-padded at window borders)
        const float* cw = branch ? cw1 : cw0;
        const float* cbs = branch ? cb1 : cb0;
        int Hsp = branch ? 2 : RESO_;
        int Wsp = branch ? RESO_ : 2;
        int hs, ws;
        if (branch == 0) { hs = tid >> 1; ws = tid & 1; }
        else             { hs = tid / RESO_; ws = tid - hs * RESO_; }

        float outv[32];
        #pragma unroll
        for (int d = 0; d < 32; d++) {
            int c = head * 32 + d;
            float l = cbs[c];
            #pragma unroll
            for (int dy = -1; dy <= 1; dy++) {
                int y = hs + dy;
                if (y < 0 || y >= Hsp) continue;
                #pragma unroll
                for (int dx = -1; dx <= 1; dx++) {
                    int x = ws + dx;
                    if (x < 0 || x >= Wsp) continue;
                    l += cw[c * 9 + (dy + 1) * 3 + (dx + 1)] *
                         Vs[(y * Wsp + x) * SLOT_STRIDE_ + d];
                }
            }
            outv[d] = acc[d] * inv + l;
        }

        int pix;
        if (branch == 0) pix = hs * RESO_ + slot * 2 + ws;
        else             pix = (slot * 2 + hs) * RESO_ + ws;
        float* op = outp + ((size_t)(b * L_ + pix)) * C_ + cb;
        #pragma unroll
        for (int f = 0; f < 8; f++)
            *(float4*)(op + f * 4) = make_float4(outv[f*4], outv[f*4+1],
                                                 outv[f*4+2], outv[f*4+3]);
    }
}

// ---------------------------------------------------------------------------
extern "C" void kernel_launch(void* const* d_in, const int* in_sizes, int n_in,
                              void* d_out, int out_size)
{
    const float* x       = (const float*)d_in[0];
    const float* n1g     = (const float*)d_in[1];
    const float* n1b     = (const float*)d_in[2];
    const float* qkv_w   = (const float*)d_in[3];
    const float* proj_w  = (const float*)d_in[4];
    const float* proj_b  = (const float*)d_in[5];
    const float* conv_w0 = (const float*)d_in[6];
    const float* conv_b0 = (const float*)d_in[7];
    const float* conv_w1 = (const float*)d_in[8];
    const float* conv_b1 = (const float*)d_in[9];
    const float* n2g     = (const float*)d_in[10];
    const float* n2b     = (const float*)d_in[11];
    const float* fc1_w   = (const float*)d_in[12];
    const float* fc1_b   = (const float*)d_in[13];
    const float* fc2_w   = (const float*)d_in[14];
    const float* fc2_b   = (const float*)d_in[15];
    float* out = (float*)d_out;

    float *ln, *qkvb, *attn, *xr, *hid;
    cudaGetSymbolAddress((void**)&ln,   g_ln);
    cudaGetSymbolAddress((void**)&qkvb, g_qkv);
    cudaGetSymbolAddress((void**)&attn, g_attn);
    cudaGetSymbolAddress((void**)&xr,   g_x);
    cudaGetSymbolAddress((void**)&hid,  g_hid);

    const int attn_smem = (3 * TOK_ * SLOT_STRIDE_ + TOK_ * 113) * 4;  // 99008 B
    cudaFuncSetAttribute(attn_kernel,
                         cudaFuncAttributeMaxDynamicSharedMemorySize, attn_smem);

    // 1. LN1
    ln_kernel<<<M_ / 8, 256>>>(x, n1g, n1b, ln);
    // 2. QKV GEMM: [M,128] @ [128,384]
    sgemm_kernel<<<dim3(384 / BN, M_ / BM), 256>>>(ln, qkv_w, qkvb,
                                                   M_, 384, 128, nullptr, nullptr, 0);
    // 3. Fused window attention + LEPE
    attn_kernel<<<3584, 128, attn_smem>>>(qkvb, conv_w0, conv_b0, conv_w1, conv_b1, attn);
    // 4. proj GEMM + bias + residual(x) -> g_x
    sgemm_kernel<<<dim3(128 / BN, M_ / BM), 256>>>(attn, proj_w, xr,
                                                   M_, 128, 128, proj_b, x, 1);
    // 5. LN2
    ln_kernel<<<M_ / 8, 256>>>(xr, n2g, n2b, ln);
    // 6. fc1 GEMM + bias + exact GELU -> g_hid
    sgemm_kernel<<<dim3(HID_ / BN, M_ / BM), 256>>>(ln, fc1_w, hid,
                                                    M_, HID_, 128, fc1_b, nullptr, 2);
    // 7. fc2 GEMM + bias + residual(g_x) -> out
    sgemm_kernel<<<dim3(128 / BN, M_ / BM), 256>>>(hid, fc2_w, out,
                                                   M_, 128, HID_, fc2_b, xr, 3);
}

// round 3
// speedup vs baseline: 2.0368x; 2.0368x over previous
#include <cuda_runtime.h>
#include <cuda_bf16.h>
#include <math.h>
#include <stdint.h>

// Problem constants
#define BATCH_ 32
#define RESO_ 56
#define L_ (RESO_ * RESO_)          // 3136
#define C_ 128
#define M_ (BATCH_ * L_)            // 100352 rows
#define HID_ 512
#define TOK_ 112                    // window tokens (56*2)
#define NWIN_ 28                    // windows per batch per branch
#define SLOT_STRIDE_ 36             // padded head-dim stride in smem (floats)

// Scratch buffers (device globals: allocation-free)
__device__ __nv_bfloat16 g_ln  [(size_t)M_ * C_];
__device__ __nv_bfloat16 g_qkv [(size_t)M_ * 3 * C_];
__device__ __nv_bfloat16 g_attn[(size_t)M_ * C_];
__device__ float         g_x   [(size_t)M_ * C_];
__device__ __nv_bfloat16 g_hid [(size_t)M_ * HID_];
__device__ __nv_bfloat16 g_w   [196608];   // transposed bf16 weights

// ---------------------------------------------------------------------------
// PTX helpers (baseline PTX, portable to compute_103)
// ---------------------------------------------------------------------------
__device__ __forceinline__ uint32_t smem_u32(const void* p) {
    uint32_t a;
    asm("{ .reg .u64 t; cvta.to.shared.u64 t, %1; cvt.u32.u64 %0, t; }" : "=r"(a) : "l"(p));
    return a;
}
__device__ __forceinline__ void cp16(uint32_t dst, const void* src) {
    asm volatile("cp.async.cg.shared.global [%0], [%1], 16;" :: "r"(dst), "l"(src));
}
#define CP_COMMIT() asm volatile("cp.async.commit_group;" ::: "memory")
#define CP_WAIT1()  asm volatile("cp.async.wait_group 1;" ::: "memory")
#define CP_WAIT0()  asm volatile("cp.async.wait_group 0;" ::: "memory")

__device__ __forceinline__ void ldsm_x4(uint32_t& r0, uint32_t& r1,
                                        uint32_t& r2, uint32_t& r3, uint32_t addr) {
    asm volatile("ldmatrix.sync.aligned.m8n8.x4.shared.b16 {%0,%1,%2,%3}, [%4];"
                 : "=r"(r0), "=r"(r1), "=r"(r2), "=r"(r3) : "r"(addr));
}
__device__ __forceinline__ void mma_bf16(float* c, const uint32_t* a,
                                         uint32_t b0, uint32_t b1) {
    asm volatile("mma.sync.aligned.m16n8k16.row.col.f32.bf16.bf16.f32 "
                 "{%0,%1,%2,%3}, {%4,%5,%6,%7}, {%8,%9}, {%0,%1,%2,%3};"
                 : "+f"(c[0]), "+f"(c[1]), "+f"(c[2]), "+f"(c[3])
                 : "r"(a[0]), "r"(a[1]), "r"(a[2]), "r"(a[3]), "r"(b0), "r"(b1));
}

// ---------------------------------------------------------------------------
// LayerNorm: one warp per row of 128; bf16 output
// ---------------------------------------------------------------------------
__global__ __launch_bounds__(256) void ln_kernel(
    const float* __restrict__ in, const float* __restrict__ g,
    const float* __restrict__ b, __nv_bfloat16* __restrict__ out)
{
    int warp = (blockIdx.x * blockDim.x + threadIdx.x) >> 5;
    int lane = threadIdx.x & 31;
    if (warp >= M_) return;
    float4 v = ((const float4*)(in + (size_t)warp * C_))[lane];
    float s = v.x + v.y + v.z + v.w;
    #pragma unroll
    for (int o = 16; o; o >>= 1) s += __shfl_xor_sync(0xffffffffu, s, o);
    float mu = s * (1.0f / C_);
    float dx = v.x - mu, dy = v.y - mu, dz = v.z - mu, dw = v.w - mu;
    float q = dx*dx + dy*dy + dz*dz + dw*dw;
    #pragma unroll
    for (int o = 16; o; o >>= 1) q += __shfl_xor_sync(0xffffffffu, q, o);
    float rs = rsqrtf(q * (1.0f / C_) + 1e-5f);
    float4 gg = ((const float4*)g)[lane];
    float4 bb = ((const float4*)b)[lane];
    __nv_bfloat162 p0 = __floats2bfloat162_rn(dx * rs * gg.x + bb.x, dy * rs * gg.y + bb.y);
    __nv_bfloat162 p1 = __floats2bfloat162_rn(dz * rs * gg.z + bb.z, dw * rs * gg.w + bb.w);
    uint2 u;
    u.x = *reinterpret_cast<uint32_t*>(&p0);
    u.y = *reinterpret_cast<uint32_t*>(&p1);
    ((uint2*)(out + (size_t)warp * C_))[lane] = u;
}

// ---------------------------------------------------------------------------
// Weight convert + transpose: in[K,N] fp32 -> out[N,K] bf16
// ---------------------------------------------------------------------------
__global__ void convw_kernel(const float* __restrict__ in, __nv_bfloat16* __restrict__ out,
                             int K, int N)
{
    int i = blockIdx.x * 256 + threadIdx.x;
    if (i >= K * N) return;
    int n = i / K, k = i - n * K;
    out[i] = __float2bfloat16(in[(size_t)k * N + n]);
}

// ---------------------------------------------------------------------------
// bf16 HMMA GEMM: D[M,N] = A[M,K] @ Wt[N,K]^T (+ epilogue)
// Block tile 128x128, BK=32, double-buffered cp.async, 256 threads (8 warps,
// 4m x 2n, each warp 32x64 via m16n8k16).
// mode 0: write bf16           mode 1: +bias +res(fp32), write fp32
// mode 2: +bias, GELU, bf16    mode 3: +bias +res(fp32), write fp32
// Smem rows padded to 40 bf16 (80 B) -> conflict-free ldmatrix.
// ---------------------------------------------------------------------------
#define ROWB 80   // bytes per padded smem row (40 bf16)

__global__ __launch_bounds__(256) void mma_gemm_kernel(
    const __nv_bfloat16* __restrict__ A, const __nv_bfloat16* __restrict__ Bt,
    void* __restrict__ D, int N, int K,
    const float* __restrict__ bias, const float* __restrict__ res, int mode)
{
    __shared__ __align__(16) char smA[2][128 * ROWB];
    __shared__ __align__(16) char smB[2][128 * ROWB];

    int tid = threadIdx.x;
    int warp = tid >> 5;
    int lane = tid & 31;
    int wm = warp >> 1;            // 0..3
    int wn = warp & 1;             // 0..1
    int mBase = blockIdx.y * 128;
    int nBase = blockIdx.x * 128;

    uint32_t sA = smem_u32(smA);
    uint32_t sB = smem_u32(smB);

    float acc[2][8][4];
    #pragma unroll
    for (int i = 0; i < 2; i++)
        #pragma unroll
        for (int j = 0; j < 8; j++)
            #pragma unroll
            for (int q = 0; q < 4; q++) acc[i][j][q] = 0.0f;

    int nkt = K >> 5;

    // tile loader: 512 x 16B transfers, 2 per thread
    auto issue = [&](int kt) {
        int buf = kt & 1;
        #pragma unroll
        for (int it = 0; it < 2; it++) {
            int idx = it * 256 + tid;
            int r = idx >> 2, c = idx & 3;
            const __nv_bfloat16* ga = A  + (size_t)(mBase + r) * K + kt * 32 + c * 8;
            const __nv_bfloat16* gb = Bt + (size_t)(nBase + r) * K + kt * 32 + c * 8;
            uint32_t off = (uint32_t)(r * ROWB + c * 16);
            cp16(sA + buf * (128 * ROWB) + off, ga);
            cp16(sB + buf * (128 * ROWB) + off, gb);
        }
    };

    issue(0);
    CP_COMMIT();

    for (int kt = 0; kt < nkt; kt++) {
        if (kt + 1 < nkt) {
            issue(kt + 1);
            CP_COMMIT();
            CP_WAIT1();
        } else {
            CP_WAIT0();
        }
        __syncthreads();

        uint32_t aB = sA + (kt & 1) * (128 * ROWB);
        uint32_t bB = sB + (kt & 1) * (128 * ROWB);

        #pragma unroll
        for (int ks = 0; ks < 2; ks++) {
            // A fragments: two 16-row m-tiles
            uint32_t af[2][4];
            #pragma unroll
            for (int mt = 0; mt < 2; mt++) {
                int row = wm * 32 + mt * 16 + (lane & 15);
                int koff = ks * 16 + ((lane >> 4) << 3);
                ldsm_x4(af[mt][0], af[mt][1], af[mt][2], af[mt][3],
                        aB + row * ROWB + koff * 2);
            }
            // B fragments: 8 n-tiles of 8, loaded as 4 x4-ldmatrix
            uint32_t bf[4][4];
            #pragma unroll
            for (int nt2 = 0; nt2 < 4; nt2++) {
                int row = wn * 64 + nt2 * 16 + (((lane >> 4) & 1) << 3) + (lane & 7);
                int koff = ks * 16 + (((lane >> 3) & 1) << 3);
                ldsm_x4(bf[nt2][0], bf[nt2][1], bf[nt2][2], bf[nt2][3],
                        bB + row * ROWB + koff * 2);
            }
            #pragma unroll
            for (int mt = 0; mt < 2; mt++)
                #pragma unroll
                for (int nt = 0; nt < 8; nt++)
                    mma_bf16(acc[mt][nt], af[mt],
                             bf[nt >> 1][(nt & 1) * 2], bf[nt >> 1][(nt & 1) * 2 + 1]);
        }
        __syncthreads();
    }

    // Epilogue
    int lr = lane >> 2;            // 0..7
    int lc = (lane & 3) * 2;
    #pragma unroll
    for (int mt = 0; mt < 2; mt++) {
        int r0 = mBase + wm * 32 + mt * 16 + lr;
        #pragma unroll
        for (int nt = 0; nt < 8; nt++) {
            int col = nBase + wn * 64 + nt * 8 + lc;
            float v0 = acc[mt][nt][0], v1 = acc[mt][nt][1];
            float v2 = acc[mt][nt][2], v3 = acc[mt][nt][3];
            if (mode >= 1) {
                float2 bb = *(const float2*)(bias + col);
                v0 += bb.x; v1 += bb.y; v2 += bb.x; v3 += bb.y;
            }
            if (mode == 1 || mode == 3) {
                float2 ra = *(const float2*)(res + (size_t)r0 * N + col);
                float2 rb = *(const float2*)(res + (size_t)(r0 + 8) * N + col);
                v0 += ra.x; v1 += ra.y; v2 += rb.x; v3 += rb.y;
                float* op = (float*)D;
                *(float2*)(op + (size_t)r0 * N + col)       = make_float2(v0, v1);
                *(float2*)(op + (size_t)(r0 + 8) * N + col) = make_float2(v2, v3);
            } else {
                if (mode == 2) {
                    v0 = 0.5f * v0 * (1.0f + erff(v0 * 0.70710678118654752f));
                    v1 = 0.5f * v1 * (1.0f + erff(v1 * 0.70710678118654752f));
                    v2 = 0.5f * v2 * (1.0f + erff(v2 * 0.70710678118654752f));
                    v3 = 0.5f * v3 * (1.0f + erff(v3 * 0.70710678118654752f));
                }
                __nv_bfloat16* op = (__nv_bfloat16*)D;
                __nv_bfloat162 pa = __floats2bfloat162_rn(v0, v1);
                __nv_bfloat162 pb = __floats2bfloat162_rn(v2, v3);
                *(__nv_bfloat162*)(op + (size_t)r0 * N + col)       = pa;
                *(__nv_bfloat162*)(op + (size_t)(r0 + 8) * N + col) = pb;
            }
        }
    }
}

// ---------------------------------------------------------------------------
// Fused window attention + LEPE (bf16 in/out, fp32 math).
// One block per (branch, window, head): 3584 blocks, 128 threads.
// ---------------------------------------------------------------------------
__device__ __forceinline__ void unpack8(uint4 u, float* dst, float scale) {
    float2 f0 = __bfloat1622float2(*reinterpret_cast<__nv_bfloat162*>(&u.x));
    float2 f1 = __bfloat1622float2(*reinterpret_cast<__nv_bfloat162*>(&u.y));
    float2 f2 = __bfloat1622float2(*reinterpret_cast<__nv_bfloat162*>(&u.z));
    float2 f3 = __bfloat1622float2(*reinterpret_cast<__nv_bfloat162*>(&u.w));
    dst[0] = f0.x * scale; dst[1] = f0.y * scale;
    dst[2] = f1.x * scale; dst[3] = f1.y * scale;
    dst[4] = f2.x * scale; dst[5] = f2.y * scale;
    dst[6] = f3.x * scale; dst[7] = f3.y * scale;
}

__global__ __launch_bounds__(128) void attn_kernel(
    const __nv_bfloat16* __restrict__ qkv,
    const float* __restrict__ cw0, const float* __restrict__ cb0,
    const float* __restrict__ cw1, const float* __restrict__ cb1,
    __nv_bfloat16* __restrict__ outp)
{
    extern __shared__ float smf[];
    float* Qs = smf;
    float* Ks = smf + TOK_ * SLOT_STRIDE_;
    float* Vs = smf + 2 * TOK_ * SLOT_STRIDE_;
    float* Ss = smf + 3 * TOK_ * SLOT_STRIDE_;  // 112 * 113

    int bid = blockIdx.x;
    int branch = bid / 1792;
    int rem = bid - branch * 1792;
    int win = rem >> 1;
    int head = rem & 1;
    int b = win / NWIN_;
    int slot = win - b * NWIN_;
    int cb = branch * 64 + head * 32;
    int tid = threadIdx.x;
    const float scale = 0.17677669529663687f;

    for (int idx = tid; idx < TOK_ * 4; idx += 128) {
        int t = idx >> 2;
        int f = idx & 3;
        int pix;
        if (branch == 0) {
            pix = (t >> 1) * RESO_ + slot * 2 + (t & 1);
        } else {
            int hs = t / RESO_;
            pix = (slot * 2 + hs) * RESO_ + (t - hs * RESO_);
        }
        size_t ro = ((size_t)(b * L_ + pix)) * 384 + cb + f * 8;
        uint4 qx = *(const uint4*)(qkv + ro);
        uint4 kx = *(const uint4*)(qkv + ro + 128);
        uint4 vx = *(const uint4*)(qkv + ro + 256);
        unpack8(qx, Qs + t * SLOT_STRIDE_ + f * 8, scale);
        unpack8(kx, Ks + t * SLOT_STRIDE_ + f * 8, 1.0f);
        unpack8(vx, Vs + t * SLOT_STRIDE_ + f * 8, 1.0f);
    }
    __syncthreads();

    if (tid < TOK_) {
        float qr[32];
        #pragma unroll
        for (int d = 0; d < 32; d++) qr[d] = Qs[tid * SLOT_STRIDE_ + d];

        float* srow = Ss + tid * 113;
        float m = -1e30f;
        for (int k = 0; k < TOK_; k++) {
            const float4* kp = (const float4*)(Ks + k * SLOT_STRIDE_);
            float s = 0.0f;
            #pragma unroll
            for (int f = 0; f < 8; f++) {
                float4 kv = kp[f];
                s += qr[f*4]   * kv.x + qr[f*4+1] * kv.y +
                     qr[f*4+2] * kv.z + qr[f*4+3] * kv.w;
            }
            srow[k] = s;
            m = fmaxf(m, s);
        }
        float sum = 0.0f;
        for (int k = 0; k < TOK_; k++) {
            float p = __expf(srow[k] - m);
            srow[k] = p;
            sum += p;
        }
        float inv = 1.0f / sum;

        float acc[32];
        #pragma unroll
        for (int d = 0; d < 32; d++) acc[d] = 0.0f;
        for (int k = 0; k < TOK_; k++) {
            float p = srow[k];
            const float4* vp = (const float4*)(Vs + k * SLOT_STRIDE_);
            #pragma unroll
            for (int f = 0; f < 8; f++) {
                float4 vv = vp[f];
                acc[f*4]   += p * vv.x;
                acc[f*4+1] += p * vv.y;
                acc[f*4+2] += p * vv.z;
                acc[f*4+3] += p * vv.w;
            }
        }

        const float* cw = branch ? cw1 : cw0;
        const float* cbs = branch ? cb1 : cb0;
        int Hsp = branch ? 2 : RESO_;
        int Wsp = branch ? RESO_ : 2;
        int hs, ws;
        if (branch == 0) { hs = tid >> 1; ws = tid & 1; }
        else             { hs = tid / RESO_; ws = tid - hs * RESO_; }

        float outv[32];
        #pragma unroll
        for (int d = 0; d < 32; d++) {
            int c = head * 32 + d;
            float l = cbs[c];
            #pragma unroll
            for (int dy = -1; dy <= 1; dy++) {
                int y = hs + dy;
                if (y < 0 || y >= Hsp) continue;
                #pragma unroll
                for (int dx = -1; dx <= 1; dx++) {
                    int x = ws + dx;
                    if (x < 0 || x >= Wsp) continue;
                    l += cw[c * 9 + (dy + 1) * 3 + (dx + 1)] *
                         Vs[(y * Wsp + x) * SLOT_STRIDE_ + d];
                }
            }
            outv[d] = acc[d] * inv + l;
        }

        int pix;
        if (branch == 0) pix = hs * RESO_ + slot * 2 + ws;
        else             pix = (slot * 2 + hs) * RESO_ + ws;
        __nv_bfloat16* op = outp + ((size_t)(b * L_ + pix)) * C_ + cb;
        #pragma unroll
        for (int g8 = 0; g8 < 4; g8++) {
            __nv_bfloat162 q0 = __floats2bfloat162_rn(outv[g8*8+0], outv[g8*8+1]);
            __nv_bfloat162 q1 = __floats2bfloat162_rn(outv[g8*8+2], outv[g8*8+3]);
            __nv_bfloat162 q2 = __floats2bfloat162_rn(outv[g8*8+4], outv[g8*8+5]);
            __nv_bfloat162 q3 = __floats2bfloat162_rn(outv[g8*8+6], outv[g8*8+7]);
            uint4 u;
            u.x = *reinterpret_cast<uint32_t*>(&q0);
            u.y = *reinterpret_cast<uint32_t*>(&q1);
            u.z = *reinterpret_cast<uint32_t*>(&q2);
            u.w = *reinterpret_cast<uint32_t*>(&q3);
            *(uint4*)(op + g8 * 8) = u;
        }
    }
}

// ---------------------------------------------------------------------------
extern "C" void kernel_launch(void* const* d_in, const int* in_sizes, int n_in,
                              void* d_out, int out_size)
{
    const float* x       = (const float*)d_in[0];
    const float* n1g     = (const float*)d_in[1];
    const float* n1b     = (const float*)d_in[2];
    const float* qkv_w   = (const float*)d_in[3];
    const float* proj_w  = (const float*)d_in[4];
    const float* proj_b  = (const float*)d_in[5];
    const float* conv_w0 = (const float*)d_in[6];
    const float* conv_b0 = (const float*)d_in[7];
    const float* conv_w1 = (const float*)d_in[8];
    const float* conv_b1 = (const float*)d_in[9];
    const float* n2g     = (const float*)d_in[10];
    const float* n2b     = (const float*)d_in[11];
    const float* fc1_w   = (const float*)d_in[12];
    const float* fc1_b   = (const float*)d_in[13];
    const float* fc2_w   = (const float*)d_in[14];
    const float* fc2_b   = (const float*)d_in[15];
    float* out = (float*)d_out;

    __nv_bfloat16 *ln, *qkvb, *attn, *hid, *wts;
    float *xr;
    cudaGetSymbolAddress((void**)&ln,   g_ln);
    cudaGetSymbolAddress((void**)&qkvb, g_qkv);
    cudaGetSymbolAddress((void**)&attn, g_attn);
    cudaGetSymbolAddress((void**)&xr,   g_x);
    cudaGetSymbolAddress((void**)&hid,  g_hid);
    cudaGetSymbolAddress((void**)&wts,  g_w);

    __nv_bfloat16* w_qkv = wts;                 // [384,128]
    __nv_bfloat16* w_prj = wts + 49152;         // [128,128]
    __nv_bfloat16* w_fc1 = wts + 65536;         // [512,128]
    __nv_bfloat16* w_fc2 = wts + 131072;        // [128,512]

    const int attn_smem = (3 * TOK_ * SLOT_STRIDE_ + TOK_ * 113) * 4;  // 99008 B
    cudaFuncSetAttribute(attn_kernel,
                         cudaFuncAttributeMaxDynamicSharedMemorySize, attn_smem);

    // 0. convert + transpose weights to bf16
    convw_kernel<<<(49152 + 255) / 256, 256>>>(qkv_w,  w_qkv, 128, 384);
    convw_kernel<<<(16384 + 255) / 256, 256>>>(proj_w, w_prj, 128, 128);
    convw_kernel<<<(65536 + 255) / 256, 256>>>(fc1_w,  w_fc1, 128, 512);
    convw_kernel<<<(65536 + 255) / 256, 256>>>(fc2_w,  w_fc2, 512, 128);

    // 1. LN1 -> bf16
    ln_kernel<<<M_ / 8, 256>>>(x, n1g, n1b, ln);
    // 2. QKV GEMM -> bf16
    mma_gemm_kernel<<<dim3(3, M_ / 128), 256>>>(ln, w_qkv, qkvb, 384, 128,
                                                nullptr, nullptr, 0);
    // 3. Fused window attention + LEPE -> bf16
    attn_kernel<<<3584, 128, attn_smem>>>(qkvb, conv_w0, conv_b0, conv_w1, conv_b1, attn);
    // 4. proj GEMM + bias + residual(x) -> fp32 xr
    mma_gemm_kernel<<<dim3(1, M_ / 128), 256>>>(attn, w_prj, xr, 128, 128,
                                                proj_b, x, 1);
    // 5. LN2 -> bf16
    ln_kernel<<<M_ / 8, 256>>>(xr, n2g, n2b, ln);
    // 6. fc1 GEMM + bias + GELU -> bf16
    mma_gemm_kernel<<<dim3(4, M_ / 128), 256>>>(ln, w_fc1, hid, 512, 128,
                                                fc1_b, nullptr, 2);
    // 7. fc2 GEMM + bias + residual(xr) -> fp32 out
    mma_gemm_kernel<<<dim3(1, M_ / 128), 256>>>(hid, w_fc2, out, 128, 512,
                                                fc2_b, xr, 3);
}

// round 4
// speedup vs baseline: 4.0036x; 1.9657x over previous
#include <cuda_runtime.h>
#include <cuda_bf16.h>
#include <math.h>
#include <stdint.h>

// Problem constants
#define BATCH_ 32
#define RESO_ 56
#define L_ (RESO_ * RESO_)          // 3136
#define C_ 128
#define M_ (BATCH_ * L_)            // 100352 rows
#define HID_ 512
#define TOK_ 112                    // window tokens (56*2)
#define NWIN_ 28                    // windows per batch per branch

// Scratch buffers (device globals: allocation-free)
__device__ __nv_bfloat16 g_ln  [(size_t)M_ * C_];
__device__ __nv_bfloat16 g_qkv [(size_t)M_ * 3 * C_];
__device__ __nv_bfloat16 g_attn[(size_t)M_ * C_];
__device__ float         g_x   [(size_t)M_ * C_];
__device__ __nv_bfloat16 g_hid [(size_t)M_ * HID_];
__device__ __nv_bfloat16 g_w   [196608];   // transposed bf16 weights

// ---------------------------------------------------------------------------
// PTX helpers (baseline PTX, portable to compute_103)
// ---------------------------------------------------------------------------
__device__ __forceinline__ uint32_t smem_u32(const void* p) {
    uint32_t a;
    asm("{ .reg .u64 t; cvta.to.shared.u64 t, %1; cvt.u32.u64 %0, t; }" : "=r"(a) : "l"(p));
    return a;
}
__device__ __forceinline__ void cp16(uint32_t dst, const void* src) {
    asm volatile("cp.async.cg.shared.global [%0], [%1], 16;" :: "r"(dst), "l"(src));
}
#define CP_COMMIT() asm volatile("cp.async.commit_group;" ::: "memory")
#define CP_WAIT1()  asm volatile("cp.async.wait_group 1;" ::: "memory")
#define CP_WAIT0()  asm volatile("cp.async.wait_group 0;" ::: "memory")

__device__ __forceinline__ void ldsm_x4(uint32_t& r0, uint32_t& r1,
                                        uint32_t& r2, uint32_t& r3, uint32_t addr) {
    asm volatile("ldmatrix.sync.aligned.m8n8.x4.shared.b16 {%0,%1,%2,%3}, [%4];"
                 : "=r"(r0), "=r"(r1), "=r"(r2), "=r"(r3) : "r"(addr));
}
__device__ __forceinline__ void ldsm_x4_t(uint32_t& r0, uint32_t& r1,
                                          uint32_t& r2, uint32_t& r3, uint32_t addr) {
    asm volatile("ldmatrix.sync.aligned.m8n8.x4.trans.shared.b16 {%0,%1,%2,%3}, [%4];"
                 : "=r"(r0), "=r"(r1), "=r"(r2), "=r"(r3) : "r"(addr));
}
__device__ __forceinline__ void mma_bf16(float* c, const uint32_t* a,
                                         uint32_t b0, uint32_t b1) {
    asm volatile("mma.sync.aligned.m16n8k16.row.col.f32.bf16.bf16.f32 "
                 "{%0,%1,%2,%3}, {%4,%5,%6,%7}, {%8,%9}, {%0,%1,%2,%3};"
                 : "+f"(c[0]), "+f"(c[1]), "+f"(c[2]), "+f"(c[3])
                 : "r"(a[0]), "r"(a[1]), "r"(a[2]), "r"(a[3]), "r"(b0), "r"(b1));
}

// ---------------------------------------------------------------------------
// LayerNorm: one warp per row of 128; bf16 output
// ---------------------------------------------------------------------------
__global__ __launch_bounds__(256) void ln_kernel(
    const float* __restrict__ in, const float* __restrict__ g,
    const float* __restrict__ b, __nv_bfloat16* __restrict__ out)
{
    int warp = (blockIdx.x * blockDim.x + threadIdx.x) >> 5;
    int lane = threadIdx.x & 31;
    if (warp >= M_) return;
    float4 v = ((const float4*)(in + (size_t)warp * C_))[lane];
    float s = v.x + v.y + v.z + v.w;
    #pragma unroll
    for (int o = 16; o; o >>= 1) s += __shfl_xor_sync(0xffffffffu, s, o);
    float mu = s * (1.0f / C_);
    float dx = v.x - mu, dy = v.y - mu, dz = v.z - mu, dw = v.w - mu;
    float q = dx*dx + dy*dy + dz*dz + dw*dw;
    #pragma unroll
    for (int o = 16; o; o >>= 1) q += __shfl_xor_sync(0xffffffffu, q, o);
    float rs = rsqrtf(q * (1.0f / C_) + 1e-5f);
    float4 gg = ((const float4*)g)[lane];
    float4 bb = ((const float4*)b)[lane];
    __nv_bfloat162 p0 = __floats2bfloat162_rn(dx * rs * gg.x + bb.x, dy * rs * gg.y + bb.y);
    __nv_bfloat162 p1 = __floats2bfloat162_rn(dz * rs * gg.z + bb.z, dw * rs * gg.w + bb.w);
    uint2 u;
    u.x = *reinterpret_cast<uint32_t*>(&p0);
    u.y = *reinterpret_cast<uint32_t*>(&p1);
    ((uint2*)(out + (size_t)warp * C_))[lane] = u;
}

// ---------------------------------------------------------------------------
// Weight convert + transpose: in[K,N] fp32 -> out[N,K] bf16
// ---------------------------------------------------------------------------
__global__ void convw_kernel(const float* __restrict__ in, __nv_bfloat16* __restrict__ out,
                             int K, int N)
{
    int i = blockIdx.x * 256 + threadIdx.x;
    if (i >= K * N) return;
    int n = i / K, k = i - n * K;
    out[i] = __float2bfloat16(in[(size_t)k * N + n]);
}

// ---------------------------------------------------------------------------
// bf16 HMMA GEMM: D[M,N] = A[M,K] @ Wt[N,K]^T (+ epilogue)
// Block tile 128x128, BK=32, double-buffered cp.async, 256 threads.
// ---------------------------------------------------------------------------
#define ROWB 80   // bytes per padded smem row (40 bf16)

__global__ __launch_bounds__(256) void mma_gemm_kernel(
    const __nv_bfloat16* __restrict__ A, const __nv_bfloat16* __restrict__ Bt,
    void* __restrict__ D, int N, int K,
    const float* __restrict__ bias, const float* __restrict__ res, int mode)
{
    __shared__ __align__(16) char smA[2][128 * ROWB];
    __shared__ __align__(16) char smB[2][128 * ROWB];

    int tid = threadIdx.x;
    int warp = tid >> 5;
    int lane = tid & 31;
    int wm = warp >> 1;
    int wn = warp & 1;
    int mBase = blockIdx.y * 128;
    int nBase = blockIdx.x * 128;

    uint32_t sA = smem_u32(smA);
    uint32_t sB = smem_u32(smB);

    float acc[2][8][4];
    #pragma unroll
    for (int i = 0; i < 2; i++)
        #pragma unroll
        for (int j = 0; j < 8; j++)
            #pragma unroll
            for (int q = 0; q < 4; q++) acc[i][j][q] = 0.0f;

    int nkt = K >> 5;

    auto issue = [&](int kt) {
        int buf = kt & 1;
        #pragma unroll
        for (int it = 0; it < 2; it++) {
            int idx = it * 256 + tid;
            int r = idx >> 2, c = idx & 3;
            const __nv_bfloat16* ga = A  + (size_t)(mBase + r) * K + kt * 32 + c * 8;
            const __nv_bfloat16* gb = Bt + (size_t)(nBase + r) * K + kt * 32 + c * 8;
            uint32_t off = (uint32_t)(r * ROWB + c * 16);
            cp16(sA + buf * (128 * ROWB) + off, ga);
            cp16(sB + buf * (128 * ROWB) + off, gb);
        }
    };

    issue(0);
    CP_COMMIT();

    for (int kt = 0; kt < nkt; kt++) {
        if (kt + 1 < nkt) {
            issue(kt + 1);
            CP_COMMIT();
            CP_WAIT1();
        } else {
            CP_WAIT0();
        }
        __syncthreads();

        uint32_t aB = sA + (kt & 1) * (128 * ROWB);
        uint32_t bB = sB + (kt & 1) * (128 * ROWB);

        #pragma unroll
        for (int ks = 0; ks < 2; ks++) {
            uint32_t af[2][4];
            #pragma unroll
            for (int mt = 0; mt < 2; mt++) {
                int row = wm * 32 + mt * 16 + (lane & 15);
                int koff = ks * 16 + ((lane >> 4) << 3);
                ldsm_x4(af[mt][0], af[mt][1], af[mt][2], af[mt][3],
                        aB + row * ROWB + koff * 2);
            }
            uint32_t bf[4][4];
            #pragma unroll
            for (int nt2 = 0; nt2 < 4; nt2++) {
                int row = wn * 64 + nt2 * 16 + (((lane >> 4) & 1) << 3) + (lane & 7);
                int koff = ks * 16 + (((lane >> 3) & 1) << 3);
                ldsm_x4(bf[nt2][0], bf[nt2][1], bf[nt2][2], bf[nt2][3],
                        bB + row * ROWB + koff * 2);
            }
            #pragma unroll
            for (int mt = 0; mt < 2; mt++)
                #pragma unroll
                for (int nt = 0; nt < 8; nt++)
                    mma_bf16(acc[mt][nt], af[mt],
                             bf[nt >> 1][(nt & 1) * 2], bf[nt >> 1][(nt & 1) * 2 + 1]);
        }
        __syncthreads();
    }

    int lr = lane >> 2;
    int lc = (lane & 3) * 2;
    #pragma unroll
    for (int mt = 0; mt < 2; mt++) {
        int r0 = mBase + wm * 32 + mt * 16 + lr;
        #pragma unroll
        for (int nt = 0; nt < 8; nt++) {
            int col = nBase + wn * 64 + nt * 8 + lc;
            float v0 = acc[mt][nt][0], v1 = acc[mt][nt][1];
            float v2 = acc[mt][nt][2], v3 = acc[mt][nt][3];
            if (mode >= 1) {
                float2 bb = *(const float2*)(bias + col);
                v0 += bb.x; v1 += bb.y; v2 += bb.x; v3 += bb.y;
            }
            if (mode == 1 || mode == 3) {
                float2 ra = *(const float2*)(res + (size_t)r0 * N + col);
                float2 rb = *(const float2*)(res + (size_t)(r0 + 8) * N + col);
                v0 += ra.x; v1 += ra.y; v2 += rb.x; v3 += rb.y;
                float* op = (float*)D;
                *(float2*)(op + (size_t)r0 * N + col)       = make_float2(v0, v1);
                *(float2*)(op + (size_t)(r0 + 8) * N + col) = make_float2(v2, v3);
            } else {
                if (mode == 2) {
                    v0 = 0.5f * v0 * (1.0f + erff(v0 * 0.70710678118654752f));
                    v1 = 0.5f * v1 * (1.0f + erff(v1 * 0.70710678118654752f));
                    v2 = 0.5f * v2 * (1.0f + erff(v2 * 0.70710678118654752f));
                    v3 = 0.5f * v3 * (1.0f + erff(v3 * 0.70710678118654752f));
                }
                __nv_bfloat16* op = (__nv_bfloat16*)D;
                __nv_bfloat162 pa = __floats2bfloat162_rn(v0, v1);
                __nv_bfloat162 pb = __floats2bfloat162_rn(v2, v3);
                *(__nv_bfloat162*)(op + (size_t)r0 * N + col)       = pa;
                *(__nv_bfloat162*)(op + (size_t)(r0 + 8) * N + col) = pb;
            }
        }
    }
}

// ---------------------------------------------------------------------------
// Flash-style HMMA window attention + fused LEPE.
// One block per (branch, window, head): 3584 blocks, 224 threads (7 warps).
// M = 112 = 7*16 (warp m-tiles), N = 112 = 14*8 (n-tiles), K = 32.
// Q/K/V tiles in smem as bf16 rows of 40 elems (80 B) -> conflict-free ldmatrix.
// S computed in register fragments, softmax via quad shuffles, P kept in
// registers (C-frag == A-frag layout), O = P@V with ldmatrix.x4.trans on V.
// LEPE (depthwise 3x3 within the window) fused into the epilogue.
// ---------------------------------------------------------------------------
#define AROW 80   // bytes per smem row in attention tiles (40 bf16)

__global__ __launch_bounds__(224) void attn_kernel(
    const __nv_bfloat16* __restrict__ qkv,
    const float* __restrict__ cw0, const float* __restrict__ cb0,
    const float* __restrict__ cw1, const float* __restrict__ cb1,
    __nv_bfloat16* __restrict__ outp)
{
    __shared__ __align__(16) char smQ[TOK_ * AROW];
    __shared__ __align__(16) char smK[TOK_ * AROW];
    __shared__ __align__(16) char smV[TOK_ * AROW];
    __shared__ float cwS[288];   // 32 ch x 9 taps for this (branch, head)
    __shared__ float cbS[32];

    int bid = blockIdx.x;
    int branch = bid / 1792;
    int rem = bid - branch * 1792;
    int win = rem >> 1;
    int head = rem & 1;
    int b = win / NWIN_;
    int slot = win - b * NWIN_;
    int cb = branch * 64 + head * 32;
    int tid = threadIdx.x;
    int warp = tid >> 5;
    int lane = tid & 31;
    const float scale = 0.17677669529663687f;  // 32^-0.5

    uint32_t sQ = smem_u32(smQ);
    uint32_t sK = smem_u32(smK);
    uint32_t sV = smem_u32(smV);

    // Load conv weights + bias for this (branch, head) into smem
    {
        const float* cw = (branch ? cw1 : cw0) + head * 32 * 9;
        const float* cbp = (branch ? cb1 : cb0) + head * 32;
        for (int i = tid; i < 288; i += 224) cwS[i] = cw[i];
        if (tid < 32) cbS[tid] = cbp[tid];
    }

    // Cooperative load of Q/K/V tiles: 3 tiles x 112 rows x 4 uint4
    for (int idx = tid; idx < 3 * TOK_ * 4; idx += 224) {
        int tile = idx / 448;
        int r2 = idx - tile * 448;
        int t = r2 >> 2;
        int q = r2 & 3;
        int pix;
        if (branch == 0) pix = (t >> 1) * RESO_ + slot * 2 + (t & 1);
        else {
            int hs = t / RESO_;
            pix = (slot * 2 + hs) * RESO_ + (t - hs * RESO_);
        }
        size_t ro = ((size_t)(b * L_ + pix)) * 384 + cb + tile * 128 + q * 8;
        uint4 v = *(const uint4*)(qkv + ro);
        char* dst = (tile == 0 ? smQ : tile == 1 ? smK : smV);
        *(uint4*)(dst + t * AROW + q * 16) = v;
    }
    __syncthreads();

    // --- S = Q @ K^T, per-warp 16x112 tile ---
    uint32_t af[2][4];
    #pragma unroll
    for (int kt = 0; kt < 2; kt++) {
        int row = warp * 16 + (lane & 15);
        int koff = kt * 16 + ((lane >> 4) << 3);
        ldsm_x4(af[kt][0], af[kt][1], af[kt][2], af[kt][3],
                sQ + row * AROW + koff * 2);
    }

    float s[14][4];
    #pragma unroll
    for (int nt = 0; nt < 14; nt++) {
        s[nt][0] = s[nt][1] = s[nt][2] = s[nt][3] = 0.0f;
        uint32_t kb[4];
        // B fragment: n = tokens (rows of K), k = d
        ldsm_x4(kb[0], kb[1], kb[2], kb[3],
                sK + (nt * 8 + (lane & 7)) * AROW + (lane >> 3) * 16);
        mma_bf16(s[nt], af[0], kb[0], kb[1]);
        mma_bf16(s[nt], af[1], kb[2], kb[3]);
    }

    // --- softmax over rows (row r = lane>>2 for c0/c1, row r+8 for c2/c3) ---
    #pragma unroll
    for (int nt = 0; nt < 14; nt++) {
        s[nt][0] *= scale; s[nt][1] *= scale;
        s[nt][2] *= scale; s[nt][3] *= scale;
    }
    float m0 = -1e30f, m1 = -1e30f;
    #pragma unroll
    for (int nt = 0; nt < 14; nt++) {
        m0 = fmaxf(m0, fmaxf(s[nt][0], s[nt][1]));
        m1 = fmaxf(m1, fmaxf(s[nt][2], s[nt][3]));
    }
    #pragma unroll
    for (int o = 1; o <= 2; o <<= 1) {
        m0 = fmaxf(m0, __shfl_xor_sync(0xffffffffu, m0, o));
        m1 = fmaxf(m1, __shfl_xor_sync(0xffffffffu, m1, o));
    }
    float sum0 = 0.0f, sum1 = 0.0f;
    uint32_t p01[14], p23[14];
    #pragma unroll
    for (int nt = 0; nt < 14; nt++) {
        float e0 = __expf(s[nt][0] - m0);
        float e1 = __expf(s[nt][1] - m0);
        float e2 = __expf(s[nt][2] - m1);
        float e3 = __expf(s[nt][3] - m1);
        sum0 += e0 + e1;
        sum1 += e2 + e3;
        __nv_bfloat162 pa = __floats2bfloat162_rn(e0, e1);
        __nv_bfloat162 pb = __floats2bfloat162_rn(e2, e3);
        p01[nt] = *reinterpret_cast<uint32_t*>(&pa);
        p23[nt] = *reinterpret_cast<uint32_t*>(&pb);
    }
    #pragma unroll
    for (int o = 1; o <= 2; o <<= 1) {
        sum0 += __shfl_xor_sync(0xffffffffu, sum0, o);
        sum1 += __shfl_xor_sync(0xffffffffu, sum1, o);
    }
    float inv0 = 1.0f / sum0;
    float inv1 = 1.0f / sum1;

    // --- O = P @ V : 4 n-tiles (d), 7 k-tiles (tokens) ---
    float oacc[4][4];
    #pragma unroll
    for (int nt = 0; nt < 4; nt++)
        oacc[nt][0] = oacc[nt][1] = oacc[nt][2] = oacc[nt][3] = 0.0f;

    #pragma unroll
    for (int kt = 0; kt < 7; kt++) {
        uint32_t pa[4] = {p01[2 * kt], p23[2 * kt], p01[2 * kt + 1], p23[2 * kt + 1]};
        uint32_t vb[4], vb2[4];
        uint32_t vaddr = sV + (kt * 16 + (lane & 15)) * AROW + (lane >> 4) * 16;
        ldsm_x4_t(vb[0],  vb[1],  vb[2],  vb[3],  vaddr);        // d 0-15
        ldsm_x4_t(vb2[0], vb2[1], vb2[2], vb2[3], vaddr + 32);   // d 16-31
        mma_bf16(oacc[0], pa, vb[0],  vb[1]);
        mma_bf16(oacc[1], pa, vb[2],  vb[3]);
        mma_bf16(oacc[2], pa, vb2[0], vb2[1]);
        mma_bf16(oacc[3], pa, vb2[2], vb2[3]);
    }

    // --- Epilogue: normalize, add LEPE, store bf16 ---
    const __nv_bfloat16* Vbf = (const __nv_bfloat16*)smV;
    int lr = lane >> 2;
    int lc = (lane & 3) * 2;
    int Hsp = branch ? 2 : RESO_;
    int Wsp = branch ? RESO_ : 2;

    #pragma unroll
    for (int half = 0; half < 2; half++) {
        int tok = warp * 16 + lr + half * 8;
        float inv = half ? inv1 : inv0;
        int hs, ws;
        if (branch == 0) { hs = tok >> 1; ws = tok & 1; }
        else             { hs = tok / RESO_; ws = tok - hs * RESO_; }
        int pix;
        if (branch == 0) pix = hs * RESO_ + slot * 2 + ws;
        else             pix = (slot * 2 + hs) * RESO_ + ws;
        __nv_bfloat16* op = outp + ((size_t)(b * L_ + pix)) * C_ + cb;

        #pragma unroll
        for (int nt = 0; nt < 4; nt++) {
            int d0 = nt * 8 + lc;
            float l0 = cbS[d0], l1 = cbS[d0 + 1];
            #pragma unroll
            for (int dy = -1; dy <= 1; dy++) {
                int y = hs + dy;
                if (y < 0 || y >= Hsp) continue;
                #pragma unroll
                for (int dx = -1; dx <= 1; dx++) {
                    int x = ws + dx;
                    if (x < 0 || x >= Wsp) continue;
                    int ntok = y * Wsp + x;
                    float2 vv = __bfloat1622float2(
                        *(const __nv_bfloat162*)(Vbf + ntok * 40 + d0));
                    int wi = (dy + 1) * 3 + (dx + 1);
                    l0 += cwS[d0 * 9 + wi] * vv.x;
                    l1 += cwS[(d0 + 1) * 9 + wi] * vv.y;
                }
            }
            float v0 = oacc[nt][half * 2]     * inv + l0;
            float v1 = oacc[nt][half * 2 + 1] * inv + l1;
            __nv_bfloat162 pr = __floats2bfloat162_rn(v0, v1);
            *(__nv_bfloat162*)(op + d0) = pr;
        }
    }
}

// ---------------------------------------------------------------------------
extern "C" void kernel_launch(void* const* d_in, const int* in_sizes, int n_in,
                              void* d_out, int out_size)
{
    const float* x       = (const float*)d_in[0];
    const float* n1g     = (const float*)d_in[1];
    const float* n1b     = (const float*)d_in[2];
    const float* qkv_w   = (const float*)d_in[3];
    const float* proj_w  = (const float*)d_in[4];
    const float* proj_b  = (const float*)d_in[5];
    const float* conv_w0 = (const float*)d_in[6];
    const float* conv_b0 = (const float*)d_in[7];
    const float* conv_w1 = (const float*)d_in[8];
    const float* conv_b1 = (const float*)d_in[9];
    const float* n2g     = (const float*)d_in[10];
    const float* n2b     = (const float*)d_in[11];
    const float* fc1_w   = (const float*)d_in[12];
    const float* fc1_b   = (const float*)d_in[13];
    const float* fc2_w   = (const float*)d_in[14];
    const float* fc2_b   = (const float*)d_in[15];
    float* out = (float*)d_out;

    __nv_bfloat16 *ln, *qkvb, *attn, *hid, *wts;
    float *xr;
    cudaGetSymbolAddress((void**)&ln,   g_ln);
    cudaGetSymbolAddress((void**)&qkvb, g_qkv);
    cudaGetSymbolAddress((void**)&attn, g_attn);
    cudaGetSymbolAddress((void**)&xr,   g_x);
    cudaGetSymbolAddress((void**)&hid,  g_hid);
    cudaGetSymbolAddress((void**)&wts,  g_w);

    __nv_bfloat16* w_qkv = wts;                 // [384,128]
    __nv_bfloat16* w_prj = wts + 49152;         // [128,128]
    __nv_bfloat16* w_fc1 = wts + 65536;         // [512,128]
    __nv_bfloat16* w_fc2 = wts + 131072;        // [128,512]

    // 0. convert + transpose weights to bf16
    convw_kernel<<<(49152 + 255) / 256, 256>>>(qkv_w,  w_qkv, 128, 384);
    convw_kernel<<<(16384 + 255) / 256, 256>>>(proj_w, w_prj, 128, 128);
    convw_kernel<<<(65536 + 255) / 256, 256>>>(fc1_w,  w_fc1, 128, 512);
    convw_kernel<<<(65536 + 255) / 256, 256>>>(fc2_w,  w_fc2, 512, 128);

    // 1. LN1 -> bf16
    ln_kernel<<<M_ / 8, 256>>>(x, n1g, n1b, ln);
    // 2. QKV GEMM -> bf16
    mma_gemm_kernel<<<dim3(3, M_ / 128), 256>>>(ln, w_qkv, qkvb, 384, 128,
                                                nullptr, nullptr, 0);
    // 3. Flash-style HMMA window attention + LEPE -> bf16
    attn_kernel<<<3584, 224>>>(qkvb, conv_w0, conv_b0, conv_w1, conv_b1, attn);
    // 4. proj GEMM + bias + residual(x) -> fp32 xr
    mma_gemm_kernel<<<dim3(1, M_ / 128), 256>>>(attn, w_prj, xr, 128, 128,
                                                proj_b, x, 1);
    // 5. LN2 -> bf16
    ln_kernel<<<M_ / 8, 256>>>(xr, n2g, n2b, ln);
    // 6. fc1 GEMM + bias + GELU -> bf16
    mma_gemm_kernel<<<dim3(4, M_ / 128), 256>>>(ln, w_fc1, hid, 512, 128,
                                                fc1_b, nullptr, 2);
    // 7. fc2 GEMM + bias + residual(xr) -> fp32 out
    mma_gemm_kernel<<<dim3(1, M_ / 128), 256>>>(hid, w_fc2, out, 128, 512,
                                                fc2_b, xr, 3);
}